// round 13
// baseline (speedup 1.0000x reference)
#include <cuda_runtime.h>
#include <cuda_bf16.h>
#include <cstdint>

#define N_BOND   100000
#define D        192
#define N_ETYPES 36
#define E_PER_T  30000
#define BATCH    256
#define N_EDGES  (N_ETYPES * E_PER_T)   // 1,080,000
#define N_SEG    (N_ETYPES * BATCH)     // 9216
#define N_OCT    (N_EDGES / 8)          // 135000

#define ROWS_PER_BLOCK 128
#define ROWS_PER_STAGE 32
#define STAGES 4
#define ROW_BYTES (D * 4)                       // 768
#define STAGE_BYTES (ROWS_PER_STAGE * ROW_BYTES) // 24576
#define DOT_BLOCKS ((N_BOND + ROWS_PER_BLOCK - 1) / ROWS_PER_BLOCK)  // 782
#define DOT_SMEM (STAGES * STAGE_BYTES + 64)    // 98368

__device__ float g_s[N_BOND];     // per-node scalar projection h[i,:] . W_out
__device__ float g_acc[N_SEG];    // segment accumulators [type*BATCH + graph]

// ---- mbarrier / bulk-copy helpers -----------------------------------------
__device__ __forceinline__ uint32_t smem_u32(const void* p) {
    uint32_t a;
    asm("{ .reg .u64 t; cvta.to.shared.u64 t, %1; cvt.u32.u64 %0, t; }"
        : "=r"(a) : "l"(p));
    return a;
}
__device__ __forceinline__ void mbar_init(uint32_t a, uint32_t n) {
    asm volatile("mbarrier.init.shared.b64 [%0], %1;" :: "r"(a), "r"(n) : "memory");
}
__device__ __forceinline__ void mbar_expect_tx(uint32_t a, uint32_t bytes) {
    asm volatile("mbarrier.arrive.expect_tx.shared.b64 _, [%0], %1;"
                 :: "r"(a), "r"(bytes) : "memory");
}
__device__ __forceinline__ void bulk_copy_g2s(uint32_t dst, const void* src,
                                              uint32_t bytes, uint32_t mbar) {
    asm volatile("cp.async.bulk.shared::cluster.global.mbarrier::complete_tx::bytes "
                 "[%0], [%1], %2, [%3];"
                 :: "r"(dst), "l"(src), "r"(bytes), "r"(mbar) : "memory");
}
__device__ __forceinline__ void mbar_wait(uint32_t a, uint32_t parity) {
    asm volatile(
        "{\n\t.reg .pred P;\n\t"
        "W%=:\n\t"
        "mbarrier.try_wait.parity.shared.b64 P, [%0], %1, 0x989680;\n\t"
        "@!P bra W%=;\n\t}"
        :: "r"(a), "r"(parity) : "memory");
}

// ---------------------------------------------------------------------------
// Kernel 1: s[row] = dot(h[row,:], W_out), TMA-fed.
// Block owns 128 rows; 4x 24KB cp.async.bulk stages all issued up front
// (96KB async in flight per block, no LDG path). Consumers compute from smem:
// half-warp per row, 4 rows per warp per stage (8 warps x 4 = 32 rows).
// Also zeroes g_acc; triggers PDL for the dependent kernels.
// ---------------------------------------------------------------------------
__global__ void dot_kernel(const float* __restrict__ h,
                           const float* __restrict__ W) {
    cudaTriggerProgrammaticLaunchCompletion();
    extern __shared__ char smem[];

    const int gtid = blockIdx.x * blockDim.x + threadIdx.x;
    if (gtid < N_SEG) g_acc[gtid] = 0.f;

    const uint32_t sbase = smem_u32(smem);
    const uint32_t mbar0 = sbase + STAGES * STAGE_BYTES;

    const int row_base   = blockIdx.x * ROWS_PER_BLOCK;
    const int rows_here  = min(ROWS_PER_BLOCK, N_BOND - row_base);
    const int stages     = rows_here / ROWS_PER_STAGE;   // 32 | 100000: exact

    if (threadIdx.x == 0) {
        #pragma unroll
        for (int s = 0; s < STAGES; s++) mbar_init(mbar0 + s * 8, 1);
    }
    __syncthreads();

    if (threadIdx.x == 0) {
        const char* gsrc = (const char*)(h + (size_t)row_base * D);
        for (int s = 0; s < stages; s++) {
            mbar_expect_tx(mbar0 + s * 8, STAGE_BYTES);
            bulk_copy_g2s(sbase + s * STAGE_BYTES, gsrc + (size_t)s * STAGE_BYTES,
                          STAGE_BYTES, mbar0 + s * 8);
        }
    }

    const int lane = threadIdx.x & 31;
    const int half = lane >> 4;
    const int hl   = lane & 15;
    const int warp = threadIdx.x >> 5;    // 0..7

    const float4* W4 = reinterpret_cast<const float4*>(W);
    const float4 w0 = W4[hl];
    const float4 w1 = W4[16 + hl];
    const float4 w2 = W4[32 + hl];

    for (int s = 0; s < stages; s++) {
        mbar_wait(mbar0 + s * 8, 0);

        // warp handles stage rows warp*4 + {0,1,2,3}; half-warp takes 2 rows
        const int r0 = warp * 4 + half;       // stage-local row (iter 0)
        const int r1 = r0 + 2;                // stage-local row (iter 1)
        const float4* p0 = reinterpret_cast<const float4*>(
            smem + s * STAGE_BYTES + r0 * ROW_BYTES);
        const float4* p1 = reinterpret_cast<const float4*>(
            smem + s * STAGE_BYTES + r1 * ROW_BYTES);

        float4 a0 = p0[hl], b0 = p0[16 + hl], c0 = p0[32 + hl];
        float4 a1 = p1[hl], b1 = p1[16 + hl], c1 = p1[32 + hl];

        float acc0 = a0.x * w0.x + a0.y * w0.y + a0.z * w0.z + a0.w * w0.w
                   + b0.x * w1.x + b0.y * w1.y + b0.z * w1.z + b0.w * w1.w
                   + c0.x * w2.x + c0.y * w2.y + c0.z * w2.z + c0.w * w2.w;
        float acc1 = a1.x * w0.x + a1.y * w0.y + a1.z * w0.z + a1.w * w0.w
                   + b1.x * w1.x + b1.y * w1.y + b1.z * w1.z + b1.w * w1.w
                   + c1.x * w2.x + c1.y * w2.y + c1.z * w2.z + c1.w * w2.w;

        #pragma unroll
        for (int off = 8; off > 0; off >>= 1) {
            acc0 += __shfl_down_sync(0xffffffffu, acc0, off, 16);
            acc1 += __shfl_down_sync(0xffffffffu, acc1, off, 16);
        }
        if (hl == 0) {
            g_s[row_base + s * ROWS_PER_STAGE + r0] = acc0;
            g_s[row_base + s * ROWS_PER_STAGE + r1] = acc1;
        }
    }
}

// ---------------------------------------------------------------------------
// Kernel 2: 8 edges per thread; PDL prologue overlaps dot's tail.
// ---------------------------------------------------------------------------
__global__ void edge_kernel(const int* __restrict__ src,
                            const int* __restrict__ seg) {
    const int idx  = blockIdx.x * blockDim.x + threadIdx.x;
    const int lane = threadIdx.x & 31;

    int4 sA = {0,0,0,0}, sB = {0,0,0,0};
    int  k[8];
    bool active = (idx < N_OCT);

    if (active) {
        const int e0 = idx * 8;
        const int t  = e0 / E_PER_T;     // 8 | 30000: pack never crosses a type
        const int4* s4p = reinterpret_cast<const int4*>(src) + idx * 2;
        const int4* g4p = reinterpret_cast<const int4*>(seg) + idx * 2;
        sA = s4p[0]; sB = s4p[1];
        int4 gA = g4p[0], gB = g4p[1];

        const int kb = t * BATCH;
        k[0] = kb + gA.x; k[1] = kb + gA.y; k[2] = kb + gA.z; k[3] = kb + gA.w;
        k[4] = kb + gB.x; k[5] = kb + gB.y; k[6] = kb + gB.z; k[7] = kb + gB.w;
    }

    cudaGridDependencySynchronize();     // dot done: g_s ready, g_acc zeroed

    float val = 0.f;
    int   key = -1;
    if (active) {
        float v[8];
        v[0] = g_s[sA.x]; v[1] = g_s[sA.y]; v[2] = g_s[sA.z]; v[3] = g_s[sA.w];
        v[4] = g_s[sB.x]; v[5] = g_s[sB.y]; v[6] = g_s[sB.z]; v[7] = g_s[sB.w];

        float acc = v[0]; int cur = k[0];
        #pragma unroll
        for (int j = 1; j < 8; j++) {
            if (k[j] == cur) acc += v[j];
            else { atomicAdd(&g_acc[cur], acc); cur = k[j]; acc = v[j]; }
        }
        val = acc; key = cur;
    }

    #pragma unroll
    for (int off = 1; off < 32; off <<= 1) {
        int   okey = __shfl_down_sync(0xffffffffu, key, off);
        float oval = __shfl_down_sync(0xffffffffu, val, off);
        if (lane + off < 32 && okey == key) val += oval;
    }
    int pkey = __shfl_up_sync(0xffffffffu, key, 1);
    if (((lane == 0) || (pkey != key)) && key >= 0) atomicAdd(&g_acc[key], val);
}

// ---------------------------------------------------------------------------
// Kernel 3: mask + softmax; PDL mask-load prologue.
// ---------------------------------------------------------------------------
__global__ void softmax_kernel(const int* __restrict__ mask,
                               float* __restrict__ out) {
    __shared__ float sv[8][N_ETYPES];
    __shared__ float sred[8];

    const int g = threadIdx.x / N_ETYPES;
    const int t = threadIdx.x % N_ETYPES;
    const int b = blockIdx.x * 8 + g;

    const int m = mask[b * N_ETYPES + t];

    cudaGridDependencySynchronize();

    float x = g_acc[t * BATCH + b];
    if (m != 0) x = -1e9f;
    sv[g][t] = x;
    __syncthreads();

    if (t == 0) {
        float mx = sv[g][0];
        #pragma unroll
        for (int i = 1; i < N_ETYPES; i++) mx = fmaxf(mx, sv[g][i]);
        sred[g] = mx;
    }
    __syncthreads();

    float e = __expf(x - sred[g]);
    sv[g][t] = e;
    __syncthreads();

    if (t == 0) {
        float s = 0.f;
        #pragma unroll
        for (int i = 0; i < N_ETYPES; i++) s += sv[g][i];
        sred[g] = s;
    }
    __syncthreads();

    out[b * N_ETYPES + t] = e / sred[g];
}

// ---------------------------------------------------------------------------
static void launch_pdl(void* fn, dim3 grid, dim3 block, void** args) {
    cudaLaunchConfig_t cfg = {};
    cfg.gridDim  = grid;
    cfg.blockDim = block;
    cfg.stream   = 0;
    cudaLaunchAttribute attr[1];
    attr[0].id = cudaLaunchAttributeProgrammaticStreamSerialization;
    attr[0].val.programmaticStreamSerializationAllowed = 1;
    cfg.attrs = attr;
    cfg.numAttrs = 1;
    cudaLaunchKernelExC(&cfg, fn, args);
}

extern "C" void kernel_launch(void* const* d_in, const int* in_sizes, int n_in,
                              void* d_out, int out_size) {
    const float* h    = (const float*)d_in[0];   // [100000,192]
    const float* Wout = (const float*)d_in[1];   // [192,1]
    const int*   src  = (const int*)d_in[2];     // [36,30000]
    const int*   seg  = (const int*)d_in[3];     // [36,30000]
    const int*   mask = (const int*)d_in[4];     // [256,36] bool -> int32
    float*       out  = (float*)d_out;           // [256,36]

    cudaFuncSetAttribute(dot_kernel,
                         cudaFuncAttributeMaxDynamicSharedMemorySize, DOT_SMEM);
    dot_kernel<<<DOT_BLOCKS, 256, DOT_SMEM>>>(h, Wout);

    {
        void* args[] = { (void*)&src, (void*)&seg };
        launch_pdl((void*)edge_kernel, dim3((N_OCT + 255) / 256), dim3(256), args);
    }
    {
        void* args[] = { (void*)&mask, (void*)&out };
        launch_pdl((void*)softmax_kernel, dim3(BATCH / 8), dim3(8 * N_ETYPES), args);
    }
}

// round 14
// speedup vs baseline: 1.1083x; 1.1083x over previous
#include <cuda_runtime.h>
#include <cuda_bf16.h>

#define N_BOND   100000
#define D        192
#define N_ETYPES 36
#define E_PER_T  30000
#define BATCH    256
#define N_EDGES  (N_ETYPES * E_PER_T)   // 1,080,000
#define N_SEG    (N_ETYPES * BATCH)     // 9216
#define N_OCT    (N_EDGES / 8)          // 135000

__device__ float g_s[N_BOND];     // per-node scalar projection h[i,:] . W_out
__device__ float g_acc[N_SEG];    // segment accumulators [type*BATCH + graph]

// ---------------------------------------------------------------------------
// Kernel 1: s[row] = dot(h[row,:], W_out).  Measured-best (R12, 15.9us):
// half-warp per row, 4 rows per warp, 6 LDG.128 in flight, one-shot blocks.
// Also zeroes g_acc; triggers PDL for dependents.
// ---------------------------------------------------------------------------
__global__ void dot_kernel(const float* __restrict__ h,
                           const float* __restrict__ W) {
    cudaTriggerProgrammaticLaunchCompletion();

    const int tid = blockIdx.x * blockDim.x + threadIdx.x;
    if (tid < N_SEG) g_acc[tid] = 0.f;

    const int lane = threadIdx.x & 31;
    const int half = lane >> 4;
    const int hl   = lane & 15;
    const int warp = tid >> 5;

    const float4* W4 = reinterpret_cast<const float4*>(W);
    const float4 w0 = W4[hl];
    const float4 w1 = W4[16 + hl];
    const float4 w2 = W4[32 + hl];

    const int row0 = 4 * warp + half;
    const int row1 = row0 + 2;
    if (row0 >= N_BOND) return;

    const float4* p0 = reinterpret_cast<const float4*>(h + (size_t)row0 * D);
    const float4* p1 = reinterpret_cast<const float4*>(h + (size_t)row1 * D);
    float4 a0 = p0[hl], b0 = p0[16 + hl], c0 = p0[32 + hl];
    float4 a1 = p1[hl], b1 = p1[16 + hl], c1 = p1[32 + hl];

    float acc0 = a0.x * w0.x + a0.y * w0.y + a0.z * w0.z + a0.w * w0.w
               + b0.x * w1.x + b0.y * w1.y + b0.z * w1.z + b0.w * w1.w
               + c0.x * w2.x + c0.y * w2.y + c0.z * w2.z + c0.w * w2.w;
    float acc1 = a1.x * w0.x + a1.y * w0.y + a1.z * w0.z + a1.w * w0.w
               + b1.x * w1.x + b1.y * w1.y + b1.z * w1.z + b1.w * w1.w
               + c1.x * w2.x + c1.y * w2.y + c1.z * w2.z + c1.w * w2.w;

    #pragma unroll
    for (int off = 8; off > 0; off >>= 1) {
        acc0 += __shfl_down_sync(0xffffffffu, acc0, off, 16);
        acc1 += __shfl_down_sync(0xffffffffu, acc1, off, 16);
    }
    if (hl == 0) {
        g_s[row0] = acc0;
        g_s[row1] = acc1;
    }
}

// ---------------------------------------------------------------------------
// Kernel 2: 8 edges per thread; PDL prologue (index loads + key computation)
// overlaps dot's tail; grid sync gates g_s gather / g_acc atomics.
// ---------------------------------------------------------------------------
__global__ void edge_kernel(const int* __restrict__ src,
                            const int* __restrict__ seg) {
    const int idx  = blockIdx.x * blockDim.x + threadIdx.x;
    const int lane = threadIdx.x & 31;

    int4 sA = {0,0,0,0}, sB = {0,0,0,0};
    int  k[8];
    bool active = (idx < N_OCT);

    if (active) {
        const int e0 = idx * 8;
        const int t  = e0 / E_PER_T;     // 8 | 30000: pack never crosses a type
        const int4* s4p = reinterpret_cast<const int4*>(src) + idx * 2;
        const int4* g4p = reinterpret_cast<const int4*>(seg) + idx * 2;
        sA = s4p[0]; sB = s4p[1];
        int4 gA = g4p[0], gB = g4p[1];

        const int kb = t * BATCH;
        k[0] = kb + gA.x; k[1] = kb + gA.y; k[2] = kb + gA.z; k[3] = kb + gA.w;
        k[4] = kb + gB.x; k[5] = kb + gB.y; k[6] = kb + gB.z; k[7] = kb + gB.w;
    }

    cudaGridDependencySynchronize();     // dot done: g_s ready, g_acc zeroed

    float val = 0.f;
    int   key = -1;
    if (active) {
        float v[8];
        v[0] = g_s[sA.x]; v[1] = g_s[sA.y]; v[2] = g_s[sA.z]; v[3] = g_s[sA.w];
        v[4] = g_s[sB.x]; v[5] = g_s[sB.y]; v[6] = g_s[sB.z]; v[7] = g_s[sB.w];

        float acc = v[0]; int cur = k[0];
        #pragma unroll
        for (int j = 1; j < 8; j++) {
            if (k[j] == cur) acc += v[j];
            else { atomicAdd(&g_acc[cur], acc); cur = k[j]; acc = v[j]; }
        }
        val = acc; key = cur;
    }

    #pragma unroll
    for (int off = 1; off < 32; off <<= 1) {
        int   okey = __shfl_down_sync(0xffffffffu, key, off);
        float oval = __shfl_down_sync(0xffffffffu, val, off);
        if (lane + off < 32 && okey == key) val += oval;
    }
    int pkey = __shfl_up_sync(0xffffffffu, key, 1);
    if (((lane == 0) || (pkey != key)) && key >= 0) atomicAdd(&g_acc[key], val);
}

// ---------------------------------------------------------------------------
// Kernel 3: mask + softmax, WARP-per-graph, shuffle-only (no smem, no
// __syncthreads, no serial 36-iter loops). Lane covers t=lane; lanes 0-3
// also cover t=32+lane. Max/sum via shfl_xor trees. PDL mask prologue.
// ---------------------------------------------------------------------------
__global__ void softmax_kernel(const int* __restrict__ mask,
                               float* __restrict__ out) {
    const int lane = threadIdx.x & 31;
    const int wid  = threadIdx.x >> 5;              // 0..7
    const int b    = blockIdx.x * 8 + wid;          // graph id

    // PDL prologue: mask reads are independent of edge_kernel.
    const int t0 = lane;                            // always < 36
    const int t1 = 32 + lane;                       // valid for lane < 4
    const int m0 = mask[b * N_ETYPES + t0];
    const int m1 = (lane < 4) ? mask[b * N_ETYPES + t1] : 1;

    cudaGridDependencySynchronize();                // g_acc final

    float x0 = g_acc[t0 * BATCH + b];
    float x1 = (lane < 4) ? g_acc[t1 * BATCH + b] : 0.f;
    if (m0 != 0) x0 = -1e9f;
    x1 = (lane < 4) ? ((m1 != 0) ? -1e9f : x1) : -3.402823466e38f;  // sentinel

    // Warp max over all 36 values
    float mx = fmaxf(x0, x1);
    #pragma unroll
    for (int off = 16; off > 0; off >>= 1)
        mx = fmaxf(mx, __shfl_xor_sync(0xffffffffu, mx, off));

    float e0 = __expf(x0 - mx);
    float e1 = __expf(x1 - mx);                     // sentinel underflows to 0

    float s = e0 + e1;
    #pragma unroll
    for (int off = 16; off > 0; off >>= 1)
        s += __shfl_xor_sync(0xffffffffu, s, off);

    const float inv = 1.f / s;
    out[b * N_ETYPES + t0] = e0 * inv;
    if (lane < 4) out[b * N_ETYPES + t1] = e1 * inv;
}

// ---------------------------------------------------------------------------
static void launch_pdl(void* fn, dim3 grid, dim3 block, void** args) {
    cudaLaunchConfig_t cfg = {};
    cfg.gridDim  = grid;
    cfg.blockDim = block;
    cfg.stream   = 0;
    cudaLaunchAttribute attr[1];
    attr[0].id = cudaLaunchAttributeProgrammaticStreamSerialization;
    attr[0].val.programmaticStreamSerializationAllowed = 1;
    cfg.attrs = attr;
    cfg.numAttrs = 1;
    cudaLaunchKernelExC(&cfg, fn, args);
}

extern "C" void kernel_launch(void* const* d_in, const int* in_sizes, int n_in,
                              void* d_out, int out_size) {
    const float* h    = (const float*)d_in[0];   // [100000,192]
    const float* Wout = (const float*)d_in[1];   // [192,1]
    const int*   src  = (const int*)d_in[2];     // [36,30000]
    const int*   seg  = (const int*)d_in[3];     // [36,30000]
    const int*   mask = (const int*)d_in[4];     // [256,36] bool -> int32
    float*       out  = (float*)d_out;           // [256,36]

    dot_kernel<<<(N_BOND + 31) / 32, 256>>>(h, Wout);

    {
        void* args[] = { (void*)&src, (void*)&seg };
        launch_pdl((void*)edge_kernel, dim3((N_OCT + 255) / 256), dim3(256), args);
    }
    {
        void* args[] = { (void*)&mask, (void*)&out };
        launch_pdl((void*)softmax_kernel, dim3(BATCH / 8), dim3(256), args);
    }
}